// round 4
// baseline (speedup 1.0000x reference)
#include <cuda_runtime.h>
#include <math_constants.h>

// CrossEntropyLoss: mean over rows of  sum_c -log_softmax(pred)[n,c] * target[n,c]
//   = mean_n [ lse_n * (sum_c t) - sum_c t*x ],  lse_n = max_n + log(sum exp(x - max_n))
// Single fused pass: each input element read exactly once (HBM-bound, ~2.1 GB total).

#define N_ROWS   8192
#define C_COLS   32000
#define C_VEC    (C_COLS / 4)   // 8000 float4 per row per tensor
#define THREADS  256
#define NWARPS   (THREADS / 32)

// Scratch for per-row losses (no cudaMalloc allowed anywhere).
__device__ float g_row_ce[N_ROWS];

__global__ void __launch_bounds__(THREADS)
ce_row_kernel(const float* __restrict__ pred, const float* __restrict__ tgt)
{
    const int row = blockIdx.x;
    const float4* __restrict__ p = reinterpret_cast<const float4*>(pred + (size_t)row * C_COLS);
    const float4* __restrict__ t = reinterpret_cast<const float4*>(tgt  + (size_t)row * C_COLS);
    const int tid = threadIdx.x;

    // Online logsumexp state + linear accumulators
    float m    = -CUDART_INF_F;  // running max
    float s    = 0.0f;           // sum exp(x - m)
    float dacc = 0.0f;           // sum t*x
    float tacc = 0.0f;           // sum t

    // 8000 vec4 / 256 threads = 31.25 iters/thread. Unroll 4 so ptxas
    // front-batches up to 8 LDG.128 per unrolled group (MLP depth).
    #pragma unroll 4
    for (int i = tid; i < C_VEC; i += THREADS) {
        float4 x = p[i];
        float4 y = t[i];

        dacc = fmaf(x.x, y.x, dacc);
        dacc = fmaf(x.y, y.y, dacc);
        dacc = fmaf(x.z, y.z, dacc);
        dacc = fmaf(x.w, y.w, dacc);
        tacc += (y.x + y.y) + (y.z + y.w);

        // local max of the 4; rescale only when it beats the running max
        // (short predicated arm — no divergence cost, ~1 exp per element total)
        float lm = fmaxf(fmaxf(x.x, x.y), fmaxf(x.z, x.w));
        if (lm > m) {
            s *= __expf(m - lm);   // first hit: s==0, __expf(-inf)=0 -> stays 0
            m = lm;
        }
        s += __expf(x.x - m) + __expf(x.y - m)
           + __expf(x.z - m) + __expf(x.w - m);
    }

    // ---- warp reduction of (m, s, dacc, tacc) ----
    #pragma unroll
    for (int off = 16; off > 0; off >>= 1) {
        float m2 = __shfl_xor_sync(0xFFFFFFFFu, m, off);
        float s2 = __shfl_xor_sync(0xFFFFFFFFu, s, off);
        float nm = fmaxf(m, m2);
        s = s * __expf(m - nm) + s2 * __expf(m2 - nm);
        m = nm;
        dacc += __shfl_xor_sync(0xFFFFFFFFu, dacc, off);
        tacc += __shfl_xor_sync(0xFFFFFFFFu, tacc, off);
    }

    // ---- block reduction across warps ----
    __shared__ float sh_m[NWARPS], sh_s[NWARPS], sh_d[NWARPS], sh_t[NWARPS];
    const int wid = tid >> 5;
    const int lid = tid & 31;
    if (lid == 0) {
        sh_m[wid] = m; sh_s[wid] = s; sh_d[wid] = dacc; sh_t[wid] = tacc;
    }
    __syncthreads();

    if (tid == 0) {
        float M = sh_m[0], S = sh_s[0], D = sh_d[0], T = sh_t[0];
        #pragma unroll
        for (int w = 1; w < NWARPS; w++) {
            float m2 = sh_m[w], s2 = sh_s[w];
            float nm = fmaxf(M, m2);
            S = S * __expf(M - nm) + s2 * __expf(m2 - nm);
            M = nm;
            D += sh_d[w];
            T += sh_t[w];
        }
        float lse = M + __logf(S);
        g_row_ce[row] = lse * T - D;
    }
}

__global__ void __launch_bounds__(THREADS)
ce_reduce_kernel(float* __restrict__ out)
{
    __shared__ float sh[THREADS];
    float acc = 0.0f;
    for (int i = threadIdx.x; i < N_ROWS; i += THREADS)
        acc += g_row_ce[i];
    sh[threadIdx.x] = acc;
    __syncthreads();
    #pragma unroll
    for (int sft = THREADS / 2; sft > 0; sft >>= 1) {
        if (threadIdx.x < sft) sh[threadIdx.x] += sh[threadIdx.x + sft];
        __syncthreads();
    }
    if (threadIdx.x == 0)
        out[0] = sh[0] * (1.0f / (float)N_ROWS);
}

extern "C" void kernel_launch(void* const* d_in, const int* in_sizes, int n_in,
                              void* d_out, int out_size)
{
    const float* pred = (const float*)d_in[0];
    const float* tgt  = (const float*)d_in[1];
    float* out = (float*)d_out;

    ce_row_kernel<<<N_ROWS, THREADS>>>(pred, tgt);
    ce_reduce_kernel<<<1, THREADS>>>(out);
}